// round 11
// baseline (speedup 1.0000x reference)
#include <cuda_runtime.h>
#include <cuda_fp16.h>

#define Ll 8
#define Kk 35
#define Sq 101
#define NP 51          // key pairs (50 full + 1 zero-padded odd slot)
#define BLOCK 128

// skv: 1792 floats. During staging: x chunk (1760 floats). During layers:
// f16 kT|vT — k = 816 u32 (51 pairs x 16 words), v = next 816 u32 (total 1632 u32).
#define SKVF 1792

// shared-weight buffer offsets (floats)
#define OWQKV 0
#define OBQKV 768
#define OWO   816
#define OBO   1072
#define OW1   1088
#define OB1   1344
#define OW2   1360
#define OB2   1616
#define OG1   1632
#define OBE1  1648
#define OG2   1664
#define OBE2  1680
#define WTOT  1696

typedef unsigned long long u64;
typedef unsigned int u32;

__device__ __forceinline__ u64 pk2(float lo, float hi) {
    u64 r; asm("mov.b64 %0, {%1, %2};" : "=l"(r) : "f"(lo), "f"(hi)); return r;
}
__device__ __forceinline__ void upk2(u64 v, float& lo, float& hi) {
    asm("mov.b64 {%0, %1}, %2;" : "=f"(lo), "=f"(hi) : "l"(v));
}
__device__ __forceinline__ u64 fma2_(u64 a, u64 b, u64 c) {
    u64 d; asm("fma.rn.f32x2 %0, %1, %2, %3;" : "=l"(d) : "l"(a), "l"(b), "l"(c)); return d;
}
__device__ __forceinline__ u64 mul2_(u64 a, u64 b) {
    u64 d; asm("mul.rn.f32x2 %0, %1, %2;" : "=l"(d) : "l"(a), "l"(b)); return d;
}
__device__ __forceinline__ u64 add2_(u64 a, u64 b) {
    u64 d; asm("add.rn.f32x2 %0, %1, %2;" : "=l"(d) : "l"(a), "l"(b)); return d;
}
__device__ __forceinline__ float ex2_(float x) {
    float e; asm("ex2.approx.f32 %0, %1;" : "=f"(e) : "f"(x)); return e;
}
// ---- f16x2 helpers ----
__device__ __forceinline__ u32 hmul2_(u32 a, u32 b) {
    u32 d; asm("mul.rn.f16x2 %0, %1, %2;" : "=r"(d) : "r"(a), "r"(b)); return d;
}
__device__ __forceinline__ u32 hfma2_(u32 a, u32 b, u32 c) {
    u32 d; asm("fma.rn.f16x2 %0, %1, %2, %3;" : "=r"(d) : "r"(a), "r"(b), "r"(c)); return d;
}
__device__ __forceinline__ u32 hadd2_(u32 a, u32 b) {
    u32 d; asm("add.rn.f16x2 %0, %1, %2;" : "=r"(d) : "r"(a), "r"(b)); return d;
}
__device__ __forceinline__ u32 hex2_(u32 x) {
    u32 e; asm("ex2.approx.f16x2 %0, %1;" : "=r"(e) : "r"(x)); return e;
}
__device__ __forceinline__ u32 cvtdup_(float x) {     // (x,x) as f16x2
    u32 d; asm("cvt.rn.f16x2.f32 %0, %1, %1;" : "=r"(d) : "f"(x)); return d;
}
__device__ __forceinline__ float hsum2f_(u32 h) {     // low+high as f32
    __half2 v = *reinterpret_cast<__half2*>(&h);
    return __low2float(v) + __high2float(v);
}

// dot of packed 16-vector a2[8] with a 16-float 16B-aligned row
__device__ __forceinline__ float dot16p(const u64* a2, const float* w) {
    const ulonglong2* w2 = reinterpret_cast<const ulonglong2*>(w);
    ulonglong2 p0 = w2[0], p1 = w2[1], p2 = w2[2], p3 = w2[3];
    u64 acc = mul2_(a2[0], p0.x);
    acc = fma2_(a2[1], p0.y, acc);
    acc = fma2_(a2[2], p1.x, acc);
    acc = fma2_(a2[3], p1.y, acc);
    acc = fma2_(a2[4], p2.x, acc);
    acc = fma2_(a2[5], p2.y, acc);
    acc = fma2_(a2[6], p3.x, acc);
    acc = fma2_(a2[7], p3.y, acc);
    float lo, hi; upk2(acc, lo, hi);
    return lo + hi;
}

__device__ __forceinline__ void ln16p(u64* io, const float* g, const float* b) {
    u64 s2 = io[0];
    #pragma unroll
    for (int i = 1; i < 8; i++) s2 = add2_(s2, io[i]);
    float slo, shi; upk2(s2, slo, shi);
    float mu = (slo + shi) * (1.f / 16.f);
    u64 nm2 = pk2(-mu, -mu);
    u64 c[8];
    #pragma unroll
    for (int i = 0; i < 8; i++) c[i] = add2_(io[i], nm2);
    u64 v2 = mul2_(c[0], c[0]);
    #pragma unroll
    for (int i = 1; i < 8; i++) v2 = fma2_(c[i], c[i], v2);
    float vlo, vhi; upk2(v2, vlo, vhi);
    float inv = rsqrtf((vlo + vhi) * (1.f / 16.f) + 1e-5f);
    u64 inv2 = pk2(inv, inv);
    const ulonglong2* g2 = reinterpret_cast<const ulonglong2*>(g);
    const ulonglong2* b2 = reinterpret_cast<const ulonglong2*>(b);
    #pragma unroll
    for (int j = 0; j < 4; j++) {
        ulonglong2 gg = g2[j], bb = b2[j];
        io[2*j]   = fma2_(mul2_(c[2*j],   inv2), gg.x, bb.x);
        io[2*j+1] = fma2_(mul2_(c[2*j+1], inv2), gg.y, bb.y);
    }
}

__global__ __launch_bounds__(BLOCK, 8) void TorrinE0_kernel(
    const float* __restrict__ x,
    const float* __restrict__ conv_w,
    const float* __restrict__ conv_b,
    const float* __restrict__ cls_emb,
    const float* __restrict__ Wqkv,
    const float* __restrict__ bqkv,
    const float* __restrict__ Wo,
    const float* __restrict__ bo,
    const float* __restrict__ W1,
    const float* __restrict__ b1,
    const float* __restrict__ W2,
    const float* __restrict__ b2,
    const float* __restrict__ ln1_g, const float* __restrict__ ln1_b,
    const float* __restrict__ ln2_g, const float* __restrict__ ln2_b,
    const float* __restrict__ lnf_g, const float* __restrict__ lnf_b,
    const float* __restrict__ end_w, const float* __restrict__ end_b,
    const float* __restrict__ head_w, const float* __restrict__ head_b,
    float* __restrict__ out)
{
    __shared__ __align__(16) float skv[SKVF];        // x chunk staging / f16 kT|vT
    __shared__ __align__(16) float sw[WTOT];
    __shared__ __align__(16) u64 shh[102 * 9];       // h2 stash, stride 9 u64
    __shared__ float sred[4];
    __shared__ float scls[16];

    const int b   = blockIdx.x;
    const int tid = threadIdx.x;
    const bool tok = (tid <= 100);

    // ---- stage conv weights + x chunk 1 (floats [0,1760)) ----
    const float* xr = x + (size_t)b * 3500;
    for (int i = tid; i < 440; i += BLOCK)
        ((float4*)skv)[i] = ((const float4*)xr)[i];
    for (int i = tid; i < 140; i += BLOCK)
        ((float4*)sw)[i] = ((const float4*)conv_w)[i];
    if (tid < 16) sw[560 + tid] = conv_b[tid];
    __syncthreads();

    // ---- conv phase 1: patches 0..49 (tokens 1..50) ----
    u64 h2[8];
    if (tid == 0) {
        #pragma unroll
        for (int i = 0; i < 8; i++) h2[i] = pk2(cls_emb[2*i], cls_emb[2*i+1]);
    } else if (tid <= 50) {
        const float* ps = &skv[(tid - 1) * Kk];
        #pragma unroll
        for (int i = 0; i < 8; i++) {
            float a0 = sw[560 + 2*i], a1 = sw[560 + 2*i + 1];
            for (int k = 0; k < Kk; k++) {
                float p = ps[k];
                a0 += p * sw[(2*i) * Kk + k];
                a1 += p * sw[(2*i+1) * Kk + k];
            }
            h2[i] = pk2(a0, a1);
        }
    }
    __syncthreads();

    // ---- stage x chunk 2 (floats [1740,3500)) ----
    for (int i = tid; i < 440; i += BLOCK)
        ((float4*)skv)[i] = ((const float4*)(xr + 1740))[i];
    __syncthreads();

    // ---- conv phase 2: patches 50..99 (tokens 51..100) ----
    if (tid >= 51 && tok) {
        const float* ps = &skv[(tid - 1) * Kk - 1740];
        #pragma unroll
        for (int i = 0; i < 8; i++) {
            float a0 = sw[560 + 2*i], a1 = sw[560 + 2*i + 1];
            for (int k = 0; k < Kk; k++) {
                float p = ps[k];
                a0 += p * sw[(2*i) * Kk + k];
                a1 += p * sw[(2*i+1) * Kk + k];
            }
            h2[i] = pk2(a0, a1);
        }
    }
    __syncthreads();   // conv reads done before k/v overwrite

    const float QS = 0.70710678118654752f * 1.44269504088896340f;  // scale * log2(e)
    // f16 half-index base: pair = tid>>1, parity = tid&1
    __half* kh = (__half*)skv;
    __half* vh = kh + 1632;           // v after 816 u32 k-words
    const int hbase = (tid >> 1) * 32 + (tid & 1);

    #pragma unroll 1
    for (int l = 0; l < Ll; l++) {
        // ---- stage layer weights ----
        for (int i = tid; i < 192; i += BLOCK)
            ((float4*)&sw[OWQKV])[i] = ((const float4*)(Wqkv + l*768))[i];
        for (int i = tid; i < 64; i += BLOCK) {
            ((float4*)&sw[OWO])[i] = ((const float4*)(Wo + l*256))[i];
            ((float4*)&sw[OW1])[i] = ((const float4*)(W1 + l*256))[i];
            ((float4*)&sw[OW2])[i] = ((const float4*)(W2 + l*256))[i];
        }
        if (tid < 48) sw[OBQKV + tid] = bqkv[l*48 + tid];
        if (tid < 16) {
            sw[OBO  + tid] = bo[l*16 + tid];
            sw[OB1  + tid] = b1[l*16 + tid];
            sw[OB2  + tid] = b2[l*16 + tid];
            sw[OG1  + tid] = ln1_g[l*16 + tid];
            sw[OBE1 + tid] = ln1_b[l*16 + tid];
            sw[OG2  + tid] = ln2_g[l*16 + tid];
            sw[OBE2 + tid] = ln2_b[l*16 + tid];
        }
        __syncthreads();

        // ---- k/v projection -> f16 transposed smem; stash h2 ----
        u64* st = &shh[tid * 9];
        if (tok) {
            #pragma unroll
            for (int h = 0; h < 8; h++) {
                float k0 = sw[OBQKV + 16 + 2*h]     + dot16p(h2, &sw[OWQKV + (16 + 2*h)*16]);
                float k1 = sw[OBQKV + 16 + 2*h + 1] + dot16p(h2, &sw[OWQKV + (17 + 2*h)*16]);
                kh[hbase + 4*h]     = __float2half_rn(k0);
                kh[hbase + 4*h + 2] = __float2half_rn(k1);
                float v0 = sw[OBQKV + 32 + 2*h]     + dot16p(h2, &sw[OWQKV + (32 + 2*h)*16]);
                float v1 = sw[OBQKV + 32 + 2*h + 1] + dot16p(h2, &sw[OWQKV + (33 + 2*h)*16]);
                vh[hbase + 4*h]     = __float2half_rn(v0);
                vh[hbase + 4*h + 2] = __float2half_rn(v1);
            }
            #pragma unroll
            for (int i = 0; i < 8; i++) st[i] = h2[i];   // stash h2 across hot loop
        } else if (tid == 101) {
            // zero-pad odd slot of pair 50: s=0 -> e=2^0=1 exactly, corrected post-loop; v=0
            #pragma unroll
            for (int h = 0; h < 8; h++) {
                kh[hbase + 4*h]     = __ushort_as_half((unsigned short)0);
                kh[hbase + 4*h + 2] = __ushort_as_half((unsigned short)0);
                vh[hbase + 4*h]     = __ushort_as_half((unsigned short)0);
                vh[hbase + 4*h + 2] = __ushort_as_half((unsigned short)0);
            }
        }
        __syncthreads();

        // ---- attention: 2 passes x 4 heads, f16x2 over 51 key-pairs ----
        if (tok) {
            u64 ctxp[8];

            #pragma unroll 1
            for (int pass = 0; pass < 2; pass++) {
                const int hb = pass * 4;

                // q projection for this pass's 4 heads (h reloaded from stash)
                u32 qb0[4], qb1[4];
                {
                    u64 ht[8];
                    #pragma unroll
                    for (int i = 0; i < 8; i++) ht[i] = st[i];
                    #pragma unroll
                    for (int i = 0; i < 4; i++) {
                        int h = hb + i;
                        float q0 = sw[OBQKV + 2*h]     + dot16p(ht, &sw[OWQKV + (2*h)*16]);
                        float q1 = sw[OBQKV + 2*h + 1] + dot16p(ht, &sw[OWQKV + (2*h+1)*16]);
                        qb0[i] = cvtdup_(q0 * QS);
                        qb1[i] = cvtdup_(q1 * QS);
                    }
                }

                u32 ssum[4], ctx0[4], ctx1[4];
                #pragma unroll
                for (int i = 0; i < 4; i++) { ssum[i] = 0u; ctx0[i] = 0u; ctx1[i] = 0u; }

                const uint4* kb = (const uint4*)skv + (hb >> 1);        // 4 uint4 per pair
                const uint4* vb = (const uint4*)skv + 204 + (hb >> 1);  // v after 204 uint4
                #pragma unroll 1
                for (int p = 0; p < NP; p++) {
                    u32 kw[8], vw[8];
                    *(uint4*)&kw[0] = kb[0]; *(uint4*)&kw[4] = kb[1];
                    *(uint4*)&vw[0] = vb[0]; *(uint4*)&vw[4] = vb[1];
                    #pragma unroll
                    for (int i = 0; i < 4; i++) {
                        u32 s = hfma2_(qb1[i], kw[2*i+1], hmul2_(qb0[i], kw[2*i]));
                        u32 e = hex2_(s);
                        ssum[i] = hadd2_(ssum[i], e);
                        ctx0[i] = hfma2_(e, vw[2*i],   ctx0[i]);
                        ctx1[i] = hfma2_(e, vw[2*i+1], ctx1[i]);
                    }
                    kb += 4; vb += 4;
                }

                #pragma unroll
                for (int i = 0; i < 4; i++) {
                    float r = __fdividef(1.f, hsum2f_(ssum[i]) - 1.f);   // remove pad e=1
                    ctxp[hb + i] = pk2(hsum2f_(ctx0[i]) * r, hsum2f_(ctx1[i]) * r);
                }
            }

            #pragma unroll
            for (int i = 0; i < 8; i++) h2[i] = st[i];   // restore h

            // out projection + residual + LN1
            u64 nh2[8];
            #pragma unroll
            for (int o = 0; o < 8; o++) {
                float d0 = sw[OBO + 2*o]     + dot16p(ctxp, &sw[OWO + (2*o)*16]);
                float d1 = sw[OBO + 2*o + 1] + dot16p(ctxp, &sw[OWO + (2*o+1)*16]);
                nh2[o] = add2_(h2[o], pk2(d0, d1));
            }
            ln16p(nh2, &sw[OG1], &sw[OBE1]);
            #pragma unroll
            for (int i = 0; i < 8; i++) h2[i] = nh2[i];

            // FFN
            u64 ff2[8];
            #pragma unroll
            for (int f = 0; f < 8; f++) {
                float f0 = fmaxf(sw[OB1 + 2*f]     + dot16p(h2, &sw[OW1 + (2*f)*16]),   0.f);
                float f1 = fmaxf(sw[OB1 + 2*f + 1] + dot16p(h2, &sw[OW1 + (2*f+1)*16]), 0.f);
                ff2[f] = pk2(f0, f1);
            }
            #pragma unroll
            for (int o = 0; o < 8; o++) {
                float d0 = sw[OB2 + 2*o]     + dot16p(ff2, &sw[OW2 + (2*o)*16]);
                float d1 = sw[OB2 + 2*o + 1] + dot16p(ff2, &sw[OW2 + (2*o+1)*16]);
                nh2[o] = add2_(h2[o], pk2(d0, d1));
            }
            ln16p(nh2, &sw[OG2], &sw[OBE2]);
            #pragma unroll
            for (int i = 0; i < 8; i++) h2[i] = nh2[i];
        }
        __syncthreads();   // all reads of skv/sw done before next layer
    }

    // ---- final LN on CLS token + head ----
    if (tid == 0) {
        float hv[16];
        #pragma unroll
        for (int i = 0; i < 8; i++) upk2(h2[i], hv[2*i], hv[2*i+1]);
        float mu = 0.f;
        #pragma unroll
        for (int d = 0; d < 16; d++) mu += hv[d];
        mu *= (1.f/16.f);
        float var = 0.f;
        #pragma unroll
        for (int d = 0; d < 16; d++) { float c = hv[d] - mu; var += c*c; }
        var *= (1.f/16.f);
        float inv = rsqrtf(var + 1e-5f);
        #pragma unroll
        for (int d = 0; d < 16; d++)
            scls[d] = (hv[d] - mu) * inv * lnf_g[d] + lnf_b[d];
    }
    __syncthreads();

    float part = 0.f;
    if (tid < 100) {
        u64 c2[8];
        #pragma unroll
        for (int i = 0; i < 8; i++) c2[i] = pk2(scls[2*i], scls[2*i+1]);
        float acc = end_b[tid] + dot16p(c2, end_w + tid * 16);
        part = acc * head_w[tid];
    }
    #pragma unroll
    for (int off = 16; off > 0; off >>= 1)
        part += __shfl_down_sync(0xffffffffu, part, off);
    if ((tid & 31) == 0) sred[tid >> 5] = part;
    __syncthreads();
    if (tid == 0) {
        float z = sred[0] + sred[1] + sred[2] + sred[3] + head_b[0];
        out[b] = 1.f / (1.f + ex2_(-z * 1.44269504088896340f));
    }
}

extern "C" void kernel_launch(void* const* d_in, const int* in_sizes, int n_in,
                              void* d_out, int out_size) {
    const float* x      = (const float*)d_in[0];
    const float* conv_w = (const float*)d_in[1];
    const float* conv_b = (const float*)d_in[2];
    const float* cls_e  = (const float*)d_in[3];
    const float* Wqkv   = (const float*)d_in[4];
    const float* bqkv   = (const float*)d_in[5];
    const float* Wo     = (const float*)d_in[6];
    const float* bo     = (const float*)d_in[7];
    const float* W1     = (const float*)d_in[8];
    const float* b1     = (const float*)d_in[9];
    const float* W2     = (const float*)d_in[10];
    const float* b2     = (const float*)d_in[11];
    const float* ln1_g  = (const float*)d_in[12];
    const float* ln1_b  = (const float*)d_in[13];
    const float* ln2_g  = (const float*)d_in[14];
    const float* ln2_b  = (const float*)d_in[15];
    const float* lnf_g  = (const float*)d_in[16];
    const float* lnf_b  = (const float*)d_in[17];
    const float* end_w  = (const float*)d_in[18];
    const float* end_b  = (const float*)d_in[19];
    const float* head_w = (const float*)d_in[20];
    const float* head_b = (const float*)d_in[21];

    int B = out_size;   // 2048
    TorrinE0_kernel<<<B, BLOCK>>>(x, conv_w, conv_b, cls_e, Wqkv, bqkv, Wo, bo,
                                  W1, b1, W2, b2, ln1_g, ln1_b, ln2_g, ln2_b,
                                  lnf_g, lnf_b, end_w, end_b, head_w, head_b,
                                  (float*)d_out);
}

// round 12
// speedup vs baseline: 1.0281x; 1.0281x over previous
#include <cuda_runtime.h>
#include <cuda_fp16.h>

#define Ll 8
#define Kk 35
#define Sq 101
#define NP 51
#define BLOCK 64

// shared-weight buffer offsets (floats)
#define OWQKV 0
#define OBQKV 768
#define OWO   816
#define OBO   1072
#define OW1   1088
#define OB1   1344
#define OW2   1360
#define OB2   1616
#define OG1   1632
#define OBE1  1648
#define OG2   1664
#define OBE2  1680
#define WTOT  1696

typedef unsigned long long u64;
typedef unsigned int u32;

__device__ __forceinline__ u64 pk2(float lo, float hi) {
    u64 r; asm("mov.b64 %0, {%1, %2};" : "=l"(r) : "f"(lo), "f"(hi)); return r;
}
__device__ __forceinline__ void upk2(u64 v, float& lo, float& hi) {
    asm("mov.b64 {%0, %1}, %2;" : "=f"(lo), "=f"(hi) : "l"(v));
}
__device__ __forceinline__ u64 fma2_(u64 a, u64 b, u64 c) {
    u64 d; asm("fma.rn.f32x2 %0, %1, %2, %3;" : "=l"(d) : "l"(a), "l"(b), "l"(c)); return d;
}
__device__ __forceinline__ u64 mul2_(u64 a, u64 b) {
    u64 d; asm("mul.rn.f32x2 %0, %1, %2;" : "=l"(d) : "l"(a), "l"(b)); return d;
}
__device__ __forceinline__ u64 add2_(u64 a, u64 b) {
    u64 d; asm("add.rn.f32x2 %0, %1, %2;" : "=l"(d) : "l"(a), "l"(b)); return d;
}
__device__ __forceinline__ float ex2_(float x) {
    float e; asm("ex2.approx.f32 %0, %1;" : "=f"(e) : "f"(x)); return e;
}
__device__ __forceinline__ u32 hmul2_(u32 a, u32 b) {
    u32 d; asm("mul.rn.f16x2 %0, %1, %2;" : "=r"(d) : "r"(a), "r"(b)); return d;
}
__device__ __forceinline__ u32 hfma2_(u32 a, u32 b, u32 c) {
    u32 d; asm("fma.rn.f16x2 %0, %1, %2, %3;" : "=r"(d) : "r"(a), "r"(b), "r"(c)); return d;
}
__device__ __forceinline__ u32 hadd2_(u32 a, u32 b) {
    u32 d; asm("add.rn.f16x2 %0, %1, %2;" : "=r"(d) : "r"(a), "r"(b)); return d;
}
__device__ __forceinline__ u32 hex2_(u32 x) {
    u32 e; asm("ex2.approx.f16x2 %0, %1;" : "=r"(e) : "r"(x)); return e;
}
// pack (lo, hi) f32 -> f16x2 (lo in low half)
__device__ __forceinline__ u32 pkh2_(float lo, float hi) {
    u32 d; asm("cvt.rn.f16x2.f32 %0, %1, %2;" : "=r"(d) : "f"(hi), "f"(lo)); return d;
}
__device__ __forceinline__ float hsum2f_(u32 h) {
    __half2 v = *reinterpret_cast<__half2*>(&h);
    return __low2float(v) + __high2float(v);
}

__device__ __forceinline__ float dot16p(const u64* a2, const float* w) {
    const ulonglong2* w2 = reinterpret_cast<const ulonglong2*>(w);
    ulonglong2 p0 = w2[0], p1 = w2[1], p2 = w2[2], p3 = w2[3];
    u64 acc = mul2_(a2[0], p0.x);
    acc = fma2_(a2[1], p0.y, acc);
    acc = fma2_(a2[2], p1.x, acc);
    acc = fma2_(a2[3], p1.y, acc);
    acc = fma2_(a2[4], p2.x, acc);
    acc = fma2_(a2[5], p2.y, acc);
    acc = fma2_(a2[6], p3.x, acc);
    acc = fma2_(a2[7], p3.y, acc);
    float lo, hi; upk2(acc, lo, hi);
    return lo + hi;
}

__device__ __forceinline__ void ln16p(u64* io, const float* g, const float* b) {
    u64 s2 = io[0];
    #pragma unroll
    for (int i = 1; i < 8; i++) s2 = add2_(s2, io[i]);
    float slo, shi; upk2(s2, slo, shi);
    float mu = (slo + shi) * (1.f / 16.f);
    u64 nm2 = pk2(-mu, -mu);
    u64 c[8];
    #pragma unroll
    for (int i = 0; i < 8; i++) c[i] = add2_(io[i], nm2);
    u64 v2 = mul2_(c[0], c[0]);
    #pragma unroll
    for (int i = 1; i < 8; i++) v2 = fma2_(c[i], c[i], v2);
    float vlo, vhi; upk2(v2, vlo, vhi);
    float inv = rsqrtf((vlo + vhi) * (1.f / 16.f) + 1e-5f);
    u64 inv2 = pk2(inv, inv);
    const ulonglong2* g2 = reinterpret_cast<const ulonglong2*>(g);
    const ulonglong2* b2 = reinterpret_cast<const ulonglong2*>(b);
    #pragma unroll
    for (int j = 0; j < 4; j++) {
        ulonglong2 gg = g2[j], bb = b2[j];
        io[2*j]   = fma2_(mul2_(c[2*j],   inv2), gg.x, bb.x);
        io[2*j+1] = fma2_(mul2_(c[2*j+1], inv2), gg.y, bb.y);
    }
}

// out-proj + residual + LN1 + FFN + residual + LN2 for one token (h2 updated in place)
__device__ __forceinline__ void token_tail(u64* h2, const u64* ctxp, const float* sw) {
    u64 nh2[8];
    #pragma unroll
    for (int o = 0; o < 8; o++) {
        float d0 = sw[OBO + 2*o]     + dot16p(ctxp, &sw[OWO + (2*o)*16]);
        float d1 = sw[OBO + 2*o + 1] + dot16p(ctxp, &sw[OWO + (2*o+1)*16]);
        nh2[o] = add2_(h2[o], pk2(d0, d1));
    }
    ln16p(nh2, &sw[OG1], &sw[OBE1]);
    #pragma unroll
    for (int i = 0; i < 8; i++) h2[i] = nh2[i];

    u64 ff2[8];
    #pragma unroll
    for (int f = 0; f < 8; f++) {
        float f0 = fmaxf(sw[OB1 + 2*f]     + dot16p(h2, &sw[OW1 + (2*f)*16]),   0.f);
        float f1 = fmaxf(sw[OB1 + 2*f + 1] + dot16p(h2, &sw[OW1 + (2*f+1)*16]), 0.f);
        ff2[f] = pkh2_(0.f, 0.f), ff2[f] = pk2(f0, f1);
    }
    #pragma unroll
    for (int o = 0; o < 8; o++) {
        float d0 = sw[OB2 + 2*o]     + dot16p(ff2, &sw[OW2 + (2*o)*16]);
        float d1 = sw[OB2 + 2*o + 1] + dot16p(ff2, &sw[OW2 + (2*o+1)*16]);
        nh2[o] = add2_(h2[o], pk2(d0, d1));
    }
    ln16p(nh2, &sw[OG2], &sw[OBE2]);
    #pragma unroll
    for (int i = 0; i < 8; i++) h2[i] = nh2[i];
}

__global__ __launch_bounds__(BLOCK, 8) void TorrinE0_kernel(
    const float* __restrict__ x,
    const float* __restrict__ conv_w,
    const float* __restrict__ conv_b,
    const float* __restrict__ cls_emb,
    const float* __restrict__ Wqkv,
    const float* __restrict__ bqkv,
    const float* __restrict__ Wo,
    const float* __restrict__ bo,
    const float* __restrict__ W1,
    const float* __restrict__ b1,
    const float* __restrict__ W2,
    const float* __restrict__ b2,
    const float* __restrict__ ln1_g, const float* __restrict__ ln1_b,
    const float* __restrict__ ln2_g, const float* __restrict__ ln2_b,
    const float* __restrict__ lnf_g, const float* __restrict__ lnf_b,
    const float* __restrict__ end_w, const float* __restrict__ end_b,
    const float* __restrict__ head_w, const float* __restrict__ head_b,
    float* __restrict__ out)
{
    // skv: x-chunk staging (<=1196 floats) / f16 kT|vT (k u32[0,816), v u32[816,1632))
    __shared__ __align__(16) float skv[1792];
    __shared__ __align__(16) float sw[WTOT];
    __shared__ __align__(16) u64 shh[102 * 9];       // per-token h2 stash / ctx park
    __shared__ float sred[2];
    __shared__ float scls[16];

    const int b   = blockIdx.x;
    const int tid = threadIdx.x;
    const bool tok = (tid <= 50);
    const bool last = (tid == 50);       // its B-token (101) is the zero pad

    u32* sku = (u32*)skv;

    // ---- conv weights ----
    for (int i = tid; i < 140; i += BLOCK)
        ((float4*)sw)[i] = ((const float4*)conv_w)[i];
    if (tid < 16) sw[560 + tid] = conv_b[tid];

    // ---- conv: 3 staged chunks; thread i owns tokens 2i (A) and 2i+1 (B) ----
    u64 h2A[8], h2B[8];
    #pragma unroll
    for (int i = 0; i < 8; i++) { h2A[i] = 0ULL; h2B[i] = 0ULL; }
    if (tid == 0) {
        #pragma unroll
        for (int i = 0; i < 8; i++) h2A[i] = pk2(cls_emb[2*i], cls_emb[2*i+1]);
    }
    const int pA = 2 * tid - 1;          // patch for token A (invalid for tid==0)
    const int pB = 2 * tid;              // patch for token B (invalid for tid==50)
    const float* xr = x + (size_t)b * 3500;

    const int coff4[3] = {0, 297, 595};
    const int ccnt4[3] = {298, 299, 280};
    const int cplo[3]  = {0, 34, 68};
    const int cphi[3]  = {33, 67, 99};
    #pragma unroll 1
    for (int c = 0; c < 3; c++) {
        __syncthreads();
        for (int i = tid; i < ccnt4[c]; i += BLOCK)
            ((float4*)skv)[i] = ((const float4*)xr)[coff4[c] + i];
        __syncthreads();
        const int foff = coff4[c] * 4;
        if (tok) {
            if (tid > 0 && pA >= cplo[c] && pA <= cphi[c]) {
                const float* ps = &skv[pA * Kk - foff];
                #pragma unroll
                for (int i = 0; i < 8; i++) {
                    float a0 = sw[560 + 2*i], a1 = sw[560 + 2*i + 1];
                    for (int k = 0; k < Kk; k++) {
                        float p = ps[k];
                        a0 += p * sw[(2*i) * Kk + k];
                        a1 += p * sw[(2*i+1) * Kk + k];
                    }
                    h2A[i] = pk2(a0, a1);
                }
            }
            if (!last && pB >= cplo[c] && pB <= cphi[c]) {
                const float* ps = &skv[pB * Kk - foff];
                #pragma unroll
                for (int i = 0; i < 8; i++) {
                    float a0 = sw[560 + 2*i], a1 = sw[560 + 2*i + 1];
                    for (int k = 0; k < Kk; k++) {
                        float p = ps[k];
                        a0 += p * sw[(2*i) * Kk + k];
                        a1 += p * sw[(2*i+1) * Kk + k];
                    }
                    h2B[i] = pk2(a0, a1);
                }
            }
        }
    }
    __syncthreads();

    const float QS = 0.70710678118654752f * 1.44269504088896340f;  // scale * log2(e)

    #pragma unroll 1
    for (int l = 0; l < Ll; l++) {
        // ---- stage layer weights ----
        for (int i = tid; i < 192; i += BLOCK)
            ((float4*)&sw[OWQKV])[i] = ((const float4*)(Wqkv + l*768))[i];
        {
            int i = tid;   // exactly 64 float4 per array
            ((float4*)&sw[OWO])[i] = ((const float4*)(Wo + l*256))[i];
            ((float4*)&sw[OW1])[i] = ((const float4*)(W1 + l*256))[i];
            ((float4*)&sw[OW2])[i] = ((const float4*)(W2 + l*256))[i];
        }
        if (tid < 48) sw[OBQKV + tid] = bqkv[l*48 + tid];
        if (tid < 16) {
            sw[OBO  + tid] = bo[l*16 + tid];
            sw[OB1  + tid] = b1[l*16 + tid];
            sw[OB2  + tid] = b2[l*16 + tid];
            sw[OG1  + tid] = ln1_g[l*16 + tid];
            sw[OBE1 + tid] = ln1_b[l*16 + tid];
            sw[OG2  + tid] = ln2_g[l*16 + tid];
            sw[OBE2 + tid] = ln2_b[l*16 + tid];
        }
        __syncthreads();

        // ---- qkv projection for both tokens; k/v packed (even=A, odd=B) u32 stores ----
        u32 qpA[8], qpB[8];               // (q0,q1) f16x2 per head, pre-scaled
        if (tok) {
            #pragma unroll
            for (int h = 0; h < 8; h++) {
                float qA0 = sw[OBQKV + 2*h]     + dot16p(h2A, &sw[OWQKV + (2*h)*16]);
                float qA1 = sw[OBQKV + 2*h + 1] + dot16p(h2A, &sw[OWQKV + (2*h+1)*16]);
                qpA[h] = pkh2_(qA0 * QS, qA1 * QS);
                float qB0 = sw[OBQKV + 2*h]     + dot16p(h2B, &sw[OWQKV + (2*h)*16]);
                float qB1 = sw[OBQKV + 2*h + 1] + dot16p(h2B, &sw[OWQKV + (2*h+1)*16]);
                qpB[h] = pkh2_(qB0 * QS, qB1 * QS);

                float kA0 = sw[OBQKV + 16 + 2*h]     + dot16p(h2A, &sw[OWQKV + (16 + 2*h)*16]);
                float kA1 = sw[OBQKV + 16 + 2*h + 1] + dot16p(h2A, &sw[OWQKV + (17 + 2*h)*16]);
                float kB0 = last ? 0.f : sw[OBQKV + 16 + 2*h]     + dot16p(h2B, &sw[OWQKV + (16 + 2*h)*16]);
                float kB1 = last ? 0.f : sw[OBQKV + 16 + 2*h + 1] + dot16p(h2B, &sw[OWQKV + (17 + 2*h)*16]);
                sku[tid*16 + 2*h]     = pkh2_(kA0, kB0);
                sku[tid*16 + 2*h + 1] = pkh2_(kA1, kB1);

                float vA0 = sw[OBQKV + 32 + 2*h]     + dot16p(h2A, &sw[OWQKV + (32 + 2*h)*16]);
                float vA1 = sw[OBQKV + 32 + 2*h + 1] + dot16p(h2A, &sw[OWQKV + (33 + 2*h)*16]);
                float vB0 = last ? 0.f : sw[OBQKV + 32 + 2*h]     + dot16p(h2B, &sw[OWQKV + (32 + 2*h)*16]);
                float vB1 = last ? 0.f : sw[OBQKV + 32 + 2*h + 1] + dot16p(h2B, &sw[OWQKV + (33 + 2*h)*16]);
                sku[816 + tid*16 + 2*h]     = pkh2_(vA0, vB0);
                sku[816 + tid*16 + 2*h + 1] = pkh2_(vA1, vB1);
            }
            // stash h2 (frees 32 regs across the hot loop)
            u64* stA = &shh[(2*tid) * 9];
            u64* stB = &shh[(2*tid + 1) * 9];
            #pragma unroll
            for (int i = 0; i < 8; i++) { stA[i] = h2A[i]; stB[i] = h2B[i]; }
        }
        __syncthreads();

        // ---- attention: 2 passes x 4 heads, 2 queries share every k/v load ----
        if (tok) {
            u64 ctxpA[8], ctxpB[8];
            #pragma unroll 1
            for (int pass = 0; pass < 2; pass++) {
                const int hb = 4 * pass;
                u32 qb0A[4], qb1A[4], qb0B[4], qb1B[4];
                #pragma unroll
                for (int j = 0; j < 4; j++) {
                    qb0A[j] = __byte_perm(qpA[hb+j], 0, 0x1010);
                    qb1A[j] = __byte_perm(qpA[hb+j], 0, 0x3232);
                    qb0B[j] = __byte_perm(qpB[hb+j], 0, 0x1010);
                    qb1B[j] = __byte_perm(qpB[hb+j], 0, 0x3232);
                }
                u32 ssA[4], c0A[4], c1A[4], ssB[4], c0B[4], c1B[4];
                #pragma unroll
                for (int j = 0; j < 4; j++) {
                    ssA[j] = 0u; c0A[j] = 0u; c1A[j] = 0u;
                    ssB[j] = 0u; c0B[j] = 0u; c1B[j] = 0u;
                }
                const uint4* kb = (const uint4*)sku + (hb >> 1);
                const uint4* vb = (const uint4*)sku + 204 + (hb >> 1);
                #pragma unroll 1
                for (int p = 0; p < NP; p++) {
                    uint4 ka = kb[0], kc = kb[1], va = vb[0], vc = vb[1];
                    kb += 4; vb += 4;
                    u32 kw[8] = {ka.x, ka.y, ka.z, ka.w, kc.x, kc.y, kc.z, kc.w};
                    u32 vw[8] = {va.x, va.y, va.z, va.w, vc.x, vc.y, vc.z, vc.w};
                    #pragma unroll
                    for (int j = 0; j < 4; j++) {
                        u32 sA = hfma2_(qb1A[j], kw[2*j+1], hmul2_(qb0A[j], kw[2*j]));
                        u32 eA = hex2_(sA);
                        ssA[j] = hadd2_(ssA[j], eA);
                        c0A[j] = hfma2_(eA, vw[2*j],   c0A[j]);
                        c1A[j] = hfma2_(eA, vw[2*j+1], c1A[j]);
                        u32 sB = hfma2_(qb1B[j], kw[2*j+1], hmul2_(qb0B[j], kw[2*j]));
                        u32 eB = hex2_(sB);
                        ssB[j] = hadd2_(ssB[j], eB);
                        c0B[j] = hfma2_(eB, vw[2*j],   c0B[j]);
                        c1B[j] = hfma2_(eB, vw[2*j+1], c1B[j]);
                    }
                }
                #pragma unroll
                for (int j = 0; j < 4; j++) {
                    float rA = __fdividef(1.f, hsum2f_(ssA[j]) - 1.f);  // pad key e=1
                    ctxpA[hb+j] = pk2(hsum2f_(c0A[j]) * rA, hsum2f_(c1A[j]) * rA);
                    float rB = __fdividef(1.f, hsum2f_(ssB[j]) - 1.f);
                    ctxpB[hb+j] = pk2(hsum2f_(c0B[j]) * rB, hsum2f_(c1B[j]) * rB);
                }
            }

            // restore A, park B's ctx in A's freed stash slot
            u64* stA = &shh[(2*tid) * 9];
            u64* stB = &shh[(2*tid + 1) * 9];
            #pragma unroll
            for (int i = 0; i < 8; i++) h2A[i] = stA[i];
            #pragma unroll
            for (int i = 0; i < 8; i++) stA[i] = ctxpB[i];

            token_tail(h2A, ctxpA, sw);

            #pragma unroll
            for (int i = 0; i < 8; i++) h2B[i] = stB[i];
            u64 cB[8];
            #pragma unroll
            for (int i = 0; i < 8; i++) cB[i] = stA[i];
            token_tail(h2B, cB, sw);
        }
        __syncthreads();   // all reads of sku/sw done before next layer
    }

    // ---- final LN on CLS (thread 0, token A) + head ----
    if (tid == 0) {
        float hv[16];
        #pragma unroll
        for (int i = 0; i < 8; i++) upk2(h2A[i], hv[2*i], hv[2*i+1]);
        float mu = 0.f;
        #pragma unroll
        for (int d = 0; d < 16; d++) mu += hv[d];
        mu *= (1.f/16.f);
        float var = 0.f;
        #pragma unroll
        for (int d = 0; d < 16; d++) { float c = hv[d] - mu; var += c*c; }
        var *= (1.f/16.f);
        float inv = rsqrtf(var + 1e-5f);
        #pragma unroll
        for (int d = 0; d < 16; d++)
            scls[d] = (hv[d] - mu) * inv * lnf_g[d] + lnf_b[d];
    }
    __syncthreads();

    float part = 0.f;
    if (tid < 50) {
        u64 c2[8];
        #pragma unroll
        for (int i = 0; i < 8; i++) c2[i] = pk2(scls[2*i], scls[2*i+1]);
        float a0 = end_b[tid]      + dot16p(c2, end_w + tid * 16);
        float a1 = end_b[tid + 50] + dot16p(c2, end_w + (tid + 50) * 16);
        part = a0 * head_w[tid] + a1 * head_w[tid + 50];
    }
    #pragma unroll
    for (int off = 16; off > 0; off >>= 1)
        part += __shfl_down_sync(0xffffffffu, part, off);
    if ((tid & 31) == 0) sred[tid >> 5] = part;
    __syncthreads();
    if (tid == 0) {
        float z = sred[0] + sred[1] + head_b[0];
        out[b] = 1.f / (1.f + ex2_(-z * 1.44269504088896340f));
    }
}

extern "C" void kernel_launch(void* const* d_in, const int* in_sizes, int n_in,
                              void* d_out, int out_size) {
    const float* x      = (const float*)d_in[0];
    const float* conv_w = (const float*)d_in[1];
    const float* conv_b = (const float*)d_in[2];
    const float* cls_e  = (const float*)d_in[3];
    const float* Wqkv   = (const float*)d_in[4];
    const float* bqkv   = (const float*)d_in[5];
    const float* Wo     = (const float*)d_in[6];
    const float* bo     = (const float*)d_in[7];
    const float* W1     = (const float*)d_in[8];
    const float* b1     = (const float*)d_in[9];
    const float* W2     = (const float*)d_in[10];
    const float* b2     = (const float*)d_in[11];
    const float* ln1_g  = (const float*)d_in[12];
    const float* ln1_b  = (const float*)d_in[13];
    const float* ln2_g  = (const float*)d_in[14];
    const float* ln2_b  = (const float*)d_in[15];
    const float* lnf_g  = (const float*)d_in[16];
    const float* lnf_b  = (const float*)d_in[17];
    const float* end_w  = (const float*)d_in[18];
    const float* end_b  = (const float*)d_in[19];
    const float* head_w = (const float*)d_in[20];
    const float* head_b = (const float*)d_in[21];

    int B = out_size;   // 2048
    TorrinE0_kernel<<<B, BLOCK>>>(x, conv_w, conv_b, cls_e, Wqkv, bqkv, Wo, bo,
                                  W1, b1, W2, b2, ln1_g, ln1_b, ln2_g, ln2_b,
                                  lnf_g, lnf_b, end_w, end_b, head_w, head_b,
                                  (float*)d_out);
}